// round 10
// baseline (speedup 1.0000x reference)
#include <cuda_runtime.h>
#include <cuda_fp16.h>
#include <cstdint>
#include <math.h>

// ============================================================================
// MotionDecoder on sm_103 (plain target -> mma.sync HMMA + ldmatrix + cp.async)
//
//   x[16,196,43,512] @ W1[43,512,512] + b1 -> GELU(erf)
//     -> @ W2 (6 or 3 wide) + b2 -> concat [B,T,168]
//
// R10: CTA tile 128x256, 512 threads (16 warps, 2m x 8n, warp tile 64x32),
//      2 CTAs/SM -> 8 warps/SMSP; halves x L2 re-reads. 2-stage ring.
//      Numerics: single-term fp16 (measured rel_err 2.96e-4).
// ============================================================================

#define J_TOT  43
#define J6N    13
#define D_DIM  512
#define BT_TOT 3136
#define OUT_W  168

#define MT     128
#define NT     256
#define KCH    64
#define NCHUNK 8
#define NTHR   512

#define TOTX  ((size_t)BT_TOT * J_TOT * D_DIM)   // 69,074,944 elems

// ---- smem byte offsets (dynamic). 2-stage ring ----
#define OFF_A   0         // [2][128 rows][128B]  = 2 x 16 KB  (RED overlaps)
#define OFF_B   32768     // [2][256 rows][128B]  = 2 x 32 KB
#define OFF_B1  98304     // 256 f32
#define OFF_W2  99328     // 256 x 8 f32
#define SMEM_SZ 107520

// ---- persistent scratch (static device arrays; no allocation) ----
__device__ __half g_W1T[(size_t)J_TOT * D_DIM * D_DIM];   // [j][n][d] fp16
__device__ __half g_xh[TOTX];                             // x fp16
__device__ float  g_part[2][BT_TOT][OUT_W];               // per-n-tile partials

#define SWZ(o) ((o) ^ (((o) >> 3) & 0x70))

static __device__ __forceinline__ uint32_t smem_u32(const void* p) {
    uint32_t a;
    asm("{ .reg .u64 t; cvta.to.shared.u64 t, %1; cvt.u32.u64 %0, t; }"
        : "=r"(a) : "l"(p));
    return a;
}

static __device__ __forceinline__ void ldsm4(uint32_t* r, uint32_t addr) {
    asm volatile("ldmatrix.sync.aligned.m8n8.x4.shared.b16 {%0,%1,%2,%3}, [%4];"
                 : "=r"(r[0]), "=r"(r[1]), "=r"(r[2]), "=r"(r[3]) : "r"(addr));
}
static __device__ __forceinline__ void ldsm2(uint32_t* r, uint32_t addr) {
    asm volatile("ldmatrix.sync.aligned.m8n8.x2.shared.b16 {%0,%1}, [%2];"
                 : "=r"(r[0]), "=r"(r[1]) : "r"(addr));
}
static __device__ __forceinline__ void mma16816(float* d, const uint32_t* a,
                                                const uint32_t* b) {
    asm volatile(
        "mma.sync.aligned.m16n8k16.row.col.f32.f16.f16.f32 "
        "{%0,%1,%2,%3}, {%4,%5,%6,%7}, {%8,%9}, {%0,%1,%2,%3};"
        : "+f"(d[0]), "+f"(d[1]), "+f"(d[2]), "+f"(d[3])
        : "r"(a[0]), "r"(a[1]), "r"(a[2]), "r"(a[3]), "r"(b[0]), "r"(b[1]));
}
static __device__ __forceinline__ void cp_async16(uint32_t dst, const void* src) {
    asm volatile("cp.async.cg.shared.global [%0], [%1], 16;"
                 :: "r"(dst), "l"(__cvta_generic_to_global(src)) : "memory");
}
#define CP_COMMIT() asm volatile("cp.async.commit_group;" ::: "memory")
#define CP_WAIT0()  asm volatile("cp.async.wait_group 0;" ::: "memory")

// ============================================================================
// prep_x: x fp32 -> fp16 (memory-bound, ~414MB traffic; HBM-saturated)
// ============================================================================
__global__ __launch_bounds__(256) void prep_x(const float* __restrict__ x) {
    size_t base = ((size_t)blockIdx.x * 256 + threadIdx.x) * 8;
    if (base >= TOTX) return;
    float4 p0 = reinterpret_cast<const float4*>(x + base)[0];
    float4 p1 = reinterpret_cast<const float4*>(x + base)[1];
    __half2 h0 = __floats2half2_rn(p0.x, p0.y);
    __half2 h1 = __floats2half2_rn(p0.z, p0.w);
    __half2 h2 = __floats2half2_rn(p1.x, p1.y);
    __half2 h3 = __floats2half2_rn(p1.z, p1.w);
    uint4 uh;
    uh.x = *reinterpret_cast<uint32_t*>(&h0);
    uh.y = *reinterpret_cast<uint32_t*>(&h1);
    uh.z = *reinterpret_cast<uint32_t*>(&h2);
    uh.w = *reinterpret_cast<uint32_t*>(&h3);
    *reinterpret_cast<uint4*>(g_xh + base) = uh;
}

// ============================================================================
// prep_w1: W1[j][d][n] fp32 -> g_W1T[j][n][d] fp16 (transpose via smem tile)
// ============================================================================
__global__ __launch_bounds__(256) void prep_w1(const float* __restrict__ W1) {
    __shared__ float tile[32][33];
    int j = blockIdx.z, n0 = blockIdx.x * 32, d0 = blockIdx.y * 32;
    int tx = threadIdx.x, ty = threadIdx.y;   // 32 x 8
    const float* src = W1 + (size_t)j * D_DIM * D_DIM;
#pragma unroll
    for (int i = 0; i < 4; i++)
        tile[ty + 8 * i][tx] = src[(size_t)(d0 + ty + 8 * i) * D_DIM + n0 + tx];
    __syncthreads();
    __half* dst = g_W1T + (size_t)j * D_DIM * D_DIM;
#pragma unroll
    for (int i = 0; i < 4; i++) {
        int n = n0 + ty + 8 * i, d = d0 + tx;
        dst[(size_t)n * D_DIM + d] = __float2half(tile[tx][ty + 8 * i]);
    }
}

// ============================================================================
// main GEMM + fused GELU + second-layer partials
// grid: (2 n-tiles, 25 m-tiles, 43 joints), 512 threads, 2 CTAs/SM
// ============================================================================
__global__ __launch_bounds__(NTHR, 2) void motion_main(
    const float* __restrict__ b1,
    const float* __restrict__ W2a, const float* __restrict__ W2b) {
    extern __shared__ char smem[];
    const uint32_t sb = smem_u32(smem);
    const int tid = threadIdx.x, lane = tid & 31, wid = tid >> 5;
    const int ntile = blockIdx.x, mtile = blockIdx.y, j = blockIdx.z;
    const int m0 = mtile * MT;
    const int warp_m = wid >> 3, warp_n = wid & 7;   // 2 x 8 warp grid

    float* b1s = reinterpret_cast<float*>(smem + OFF_B1);
    float* w2s = reinterpret_cast<float*>(smem + OFF_W2);
    float* red = reinterpret_cast<float*>(smem + OFF_A);   // overlaps A ring

    const int six = (j < J6N);
    const int odim = six ? 6 : 3;
    const int colbase = six ? j * 6 : 78 + (j - J6N) * 3;
    const float* w2p = six ? (W2a + (size_t)j * D_DIM * 6)
                           : (W2b + (size_t)(j - J6N) * D_DIM * 3);

    // ---- stage b1 / W2 n-slices (256 wide) ----
    if (tid < NT) b1s[tid] = b1[(size_t)j * D_DIM + ntile * NT + tid];
#pragma unroll
    for (int it = 0; it < 4; it++) {
        int i = tid + it * NTHR;         // 0..2047
        int n = i >> 3, o = i & 7;
        w2s[n * 8 + o] = (o < odim) ? w2p[(size_t)(ntile * NT + n) * odim + o] : 0.0f;
    }

    // ---- per-thread load constants ----
    const int arow0 = tid >> 3;          // 0..63
    const int akg = tid & 7;             // 16B group within 128B row
    const size_t xoff = (size_t)j * D_DIM + akg * 8;
    const __half* wsrc = g_W1T + ((size_t)j * D_DIM + ntile * NT) * D_DIM;

    // ---- per-lane ldmatrix address constants ----
    const int matA = lane >> 3, rA = lane & 7;
    uint32_t a_row_b[4];
#pragma unroll
    for (int mf = 0; mf < 4; mf++)
        a_row_b[mf] = (uint32_t)((warp_m * 64 + mf * 16 + rA + (matA & 1) * 8) * 128);
    const uint32_t a_kh = (uint32_t)((matA >> 1) * 16);
    const int matB = (lane >> 3) & 1, rB = lane & 7;
    uint32_t b_row_b[4];
#pragma unroll
    for (int nf = 0; nf < 4; nf++)
        b_row_b[nf] = (uint32_t)((warp_n * 32 + nf * 8 + rB) * 128);
    const uint32_t b_kh = (uint32_t)(matB * 16);

    // ---- issue one chunk of cp.async (A 128 rows + B 256 rows) into stage st ----
    auto issue_chunk = [&](int kc, int st) {
#pragma unroll
        for (int it = 0; it < 2; it++) {         // A: 128 rows
            int row = arow0 + 64 * it;
            int gm = m0 + row; if (gm >= BT_TOT) gm = BT_TOT - 1;
            uint32_t off = SWZ((uint32_t)(row * 128 + akg * 16));
            cp_async16(sb + OFF_A + st * 16384 + off,
                       g_xh + (size_t)gm * (J_TOT * D_DIM) + xoff + (size_t)kc * KCH);
        }
#pragma unroll
        for (int it = 0; it < 4; it++) {         // B: 256 rows
            int row = arow0 + 64 * it;
            uint32_t off = SWZ((uint32_t)(row * 128 + akg * 16));
            cp_async16(sb + OFF_B + st * 32768 + off,
                       wsrc + (size_t)row * D_DIM + (size_t)kc * KCH + akg * 8);
        }
    };

    // ---- prologue: chunk 0 ----
    issue_chunk(0, 0);
    CP_COMMIT();
    CP_WAIT0();
    __syncthreads();

    float c_[4][4][4];
#pragma unroll
    for (int mf = 0; mf < 4; mf++)
#pragma unroll
        for (int nf = 0; nf < 4; nf++)
#pragma unroll
            for (int e = 0; e < 4; e++) c_[mf][nf][e] = 0.0f;

    // ---- main K loop: 8 chunks of 64, double buffered ----
#pragma unroll 1
    for (int kc = 0; kc < NCHUNK; kc++) {
        const int buf = kc & 1, nbuf = buf ^ 1;
        const uint32_t sa = sb + OFF_A + buf * 16384;
        const uint32_t sbb = sb + OFF_B + buf * 32768;

        if (kc < NCHUNK - 1) {
            issue_chunk(kc + 1, nbuf);
            CP_COMMIT();
        }

#pragma unroll
        for (int s = 0; s < 4; s++) {
            uint32_t ahf[4][4], bf[4][2];
#pragma unroll
            for (int mf = 0; mf < 4; mf++) {
                uint32_t o = SWZ(a_row_b[mf] + (uint32_t)(s * 32) + a_kh);
                ldsm4(ahf[mf], sa + o);
            }
#pragma unroll
            for (int nf = 0; nf < 4; nf++) {
                uint32_t o = SWZ(b_row_b[nf] + (uint32_t)(s * 32) + b_kh);
                ldsm2(bf[nf], sbb + o);
            }
#pragma unroll
            for (int mf = 0; mf < 4; mf++)
#pragma unroll
                for (int nf = 0; nf < 4; nf++)
                    mma16816(c_[mf][nf], ahf[mf], bf[nf]);
        }
        if (kc < NCHUNK - 1) CP_WAIT0();
        __syncthreads();
    }

    // ---- epilogue: +b1, GELU(erf), second-layer partial dot, reduce ----
    const int grp = lane >> 2, qid = lane & 3;
#pragma unroll
    for (int mf = 0; mf < 4; mf++) {
        float po[2][6];
#pragma unroll
        for (int hh = 0; hh < 2; hh++)
#pragma unroll
            for (int o = 0; o < 6; o++) po[hh][o] = 0.0f;
#pragma unroll
        for (int nf = 0; nf < 4; nf++) {
            int nl = warp_n * 32 + nf * 8 + qid * 2;
#pragma unroll
            for (int e = 0; e < 4; e++) {
                int nn = nl + (e & 1);
                int hh = e >> 1;
                float hv = c_[mf][nf][e] + b1s[nn];
                float g = 0.5f * hv * (1.0f + erff(hv * 0.70710678118654752f));
#pragma unroll
                for (int o = 0; o < 6; o++)
                    po[hh][o] = fmaf(g, w2s[nn * 8 + o], po[hh][o]);
            }
        }
#pragma unroll
        for (int hh = 0; hh < 2; hh++)
#pragma unroll
            for (int o = 0; o < 6; o++) {
                float v = po[hh][o];
                v += __shfl_xor_sync(0xffffffffu, v, 1);
                v += __shfl_xor_sync(0xffffffffu, v, 2);
                po[hh][o] = v;
            }
        if (qid == 0) {
#pragma unroll
            for (int hh = 0; hh < 2; hh++) {
                int ml = warp_m * 64 + mf * 16 + grp + hh * 8;
#pragma unroll
                for (int o = 0; o < 6; o++)
                    red[warp_n * 768 + ml * 6 + o] = po[hh][o];
            }
        }
    }
    __syncthreads();

    // ---- sum the 8 warp_n partials, write per-n-tile partial to gmem ----
#pragma unroll
    for (int it = 0; it < 2; it++) {
        int i = tid + it * NTHR;                 // 0..1023, need 0..767
        if (i < 768) {
            int ml = i / 6, o = i % 6;
            float v = 0.0f;
#pragma unroll
            for (int wn = 0; wn < 8; wn++) v += red[wn * 768 + ml * 6 + o];
            int gm = m0 + ml;
            if (gm < BT_TOT && o < odim)
                g_part[ntile][gm][colbase + o] = v;
        }
    }
}

// ============================================================================
// final reduce: out = b2 + sum of 2 n-tile partials (deterministic, no atomics)
// ============================================================================
__global__ __launch_bounds__(256) void reduce_out(const float* __restrict__ b2a,
                                                  const float* __restrict__ b2b,
                                                  float* __restrict__ out) {
    int idx = blockIdx.x * 256 + threadIdx.x;
    if (idx >= BT_TOT * OUT_W) return;
    int m = idx / OUT_W, c = idx % OUT_W;
    float bias = (c < J6N * 6) ? b2a[c] : b2b[c - J6N * 6];
    out[idx] = bias + g_part[0][m][c] + g_part[1][m][c];
}

// ============================================================================
// kernel_launch
// ============================================================================
extern "C" void kernel_launch(void* const* d_in, const int* in_sizes, int n_in,
                              void* d_out, int out_size) {
    (void)in_sizes; (void)n_in; (void)out_size;
    const float* x   = (const float*)d_in[0];
    const float* W1  = (const float*)d_in[1];
    const float* b1  = (const float*)d_in[2];
    const float* W2a = (const float*)d_in[3];
    const float* b2a = (const float*)d_in[4];
    const float* W2b = (const float*)d_in[5];
    const float* b2b = (const float*)d_in[6];
    float* out = (float*)d_out;

    cudaFuncSetAttribute(motion_main,
                         cudaFuncAttributeMaxDynamicSharedMemorySize, SMEM_SZ);

    dim3 pg(16, 16, J_TOT);
    prep_w1<<<pg, dim3(32, 8)>>>(W1);

    size_t nthreads = TOTX / 8;
    prep_x<<<(unsigned)((nthreads + 255) / 256), 256>>>(x);

    dim3 g(2, 25, J_TOT);
    motion_main<<<g, NTHR, SMEM_SZ>>>(b1, W2a, W2b);

    int tot = BT_TOT * OUT_W;
    reduce_out<<<(tot + 255) / 256, 256>>>(b2a, b2b, out);
}

// round 11
// speedup vs baseline: 2.4596x; 2.4596x over previous
#include <cuda_runtime.h>
#include <cuda_fp16.h>
#include <cstdint>
#include <math.h>

// ============================================================================
// MotionDecoder on sm_103 (plain target -> mma.sync HMMA + ldmatrix + cp.async)
//
//   x[16,196,43,512] @ W1[43,512,512] + b1 -> GELU(erf)
//     -> @ W2 (6 or 3 wide) + b2 -> concat [B,T,168]
//
// R11: CTA tile 128x256, 512 threads, 1 CTA/SM, launch_bounds(512,1) -> full
//      128 regs (R10's (512,2) forced 64 regs -> accumulator spill, 2.8x
//      regression). Same 4 warps/SMSP as the 330us R9 config, but halved
//      x L2 re-reads. 3-stage cp.async ring. B fragments via paired ldsm4.
//      Numerics: single-term fp16 (measured rel_err 2.96e-4).
// ============================================================================

#define J_TOT  43
#define J6N    13
#define D_DIM  512
#define BT_TOT 3136
#define OUT_W  168

#define MT     128
#define NT     256
#define KCH    64
#define NCHUNK 8
#define NTHR   512

#define TOTX  ((size_t)BT_TOT * J_TOT * D_DIM)   // 69,074,944 elems

// ---- smem byte offsets (dynamic). 3-stage ring ----
#define OFF_A   0         // [3][128 rows][128B] = 3 x 16 KB   (RED overlaps)
#define OFF_B   49152     // [3][256 rows][128B] = 3 x 32 KB
#define OFF_B1  147456    // 256 f32
#define OFF_W2  148480    // 256 x 8 f32
#define SMEM_SZ 156672

// ---- persistent scratch (static device arrays; no allocation) ----
__device__ __half g_W1T[(size_t)J_TOT * D_DIM * D_DIM];   // [j][n][d] fp16
__device__ __half g_xh[TOTX];                             // x fp16
__device__ float  g_part[2][BT_TOT][OUT_W];               // per-n-tile partials

#define SWZ(o) ((o) ^ (((o) >> 3) & 0x70))

static __device__ __forceinline__ uint32_t smem_u32(const void* p) {
    uint32_t a;
    asm("{ .reg .u64 t; cvta.to.shared.u64 t, %1; cvt.u32.u64 %0, t; }"
        : "=r"(a) : "l"(p));
    return a;
}

static __device__ __forceinline__ void ldsm4(uint32_t* r, uint32_t addr) {
    asm volatile("ldmatrix.sync.aligned.m8n8.x4.shared.b16 {%0,%1,%2,%3}, [%4];"
                 : "=r"(r[0]), "=r"(r[1]), "=r"(r[2]), "=r"(r[3]) : "r"(addr));
}
static __device__ __forceinline__ void mma16816(float* d, const uint32_t* a,
                                                const uint32_t* b) {
    asm volatile(
        "mma.sync.aligned.m16n8k16.row.col.f32.f16.f16.f32 "
        "{%0,%1,%2,%3}, {%4,%5,%6,%7}, {%8,%9}, {%0,%1,%2,%3};"
        : "+f"(d[0]), "+f"(d[1]), "+f"(d[2]), "+f"(d[3])
        : "r"(a[0]), "r"(a[1]), "r"(a[2]), "r"(a[3]), "r"(b[0]), "r"(b[1]));
}
static __device__ __forceinline__ void cp_async16(uint32_t dst, const void* src) {
    asm volatile("cp.async.cg.shared.global [%0], [%1], 16;"
                 :: "r"(dst), "l"(__cvta_generic_to_global(src)) : "memory");
}
#define CP_COMMIT() asm volatile("cp.async.commit_group;" ::: "memory")
#define CP_WAIT0()  asm volatile("cp.async.wait_group 0;" ::: "memory")
#define CP_WAIT1()  asm volatile("cp.async.wait_group 1;" ::: "memory")

// ============================================================================
// prep_x: x fp32 -> fp16 (memory-bound, ~414MB traffic; HBM-saturated)
// ============================================================================
__global__ __launch_bounds__(256) void prep_x(const float* __restrict__ x) {
    size_t base = ((size_t)blockIdx.x * 256 + threadIdx.x) * 8;
    if (base >= TOTX) return;
    float4 p0 = reinterpret_cast<const float4*>(x + base)[0];
    float4 p1 = reinterpret_cast<const float4*>(x + base)[1];
    __half2 h0 = __floats2half2_rn(p0.x, p0.y);
    __half2 h1 = __floats2half2_rn(p0.z, p0.w);
    __half2 h2 = __floats2half2_rn(p1.x, p1.y);
    __half2 h3 = __floats2half2_rn(p1.z, p1.w);
    uint4 uh;
    uh.x = *reinterpret_cast<uint32_t*>(&h0);
    uh.y = *reinterpret_cast<uint32_t*>(&h1);
    uh.z = *reinterpret_cast<uint32_t*>(&h2);
    uh.w = *reinterpret_cast<uint32_t*>(&h3);
    *reinterpret_cast<uint4*>(g_xh + base) = uh;
}

// ============================================================================
// prep_w1: W1[j][d][n] fp32 -> g_W1T[j][n][d] fp16 (transpose via smem tile)
// ============================================================================
__global__ __launch_bounds__(256) void prep_w1(const float* __restrict__ W1) {
    __shared__ float tile[32][33];
    int j = blockIdx.z, n0 = blockIdx.x * 32, d0 = blockIdx.y * 32;
    int tx = threadIdx.x, ty = threadIdx.y;   // 32 x 8
    const float* src = W1 + (size_t)j * D_DIM * D_DIM;
#pragma unroll
    for (int i = 0; i < 4; i++)
        tile[ty + 8 * i][tx] = src[(size_t)(d0 + ty + 8 * i) * D_DIM + n0 + tx];
    __syncthreads();
    __half* dst = g_W1T + (size_t)j * D_DIM * D_DIM;
#pragma unroll
    for (int i = 0; i < 4; i++) {
        int n = n0 + ty + 8 * i, d = d0 + tx;
        dst[(size_t)n * D_DIM + d] = __float2half(tile[tx][ty + 8 * i]);
    }
}

// ============================================================================
// main GEMM + fused GELU + second-layer partials
// grid: (2 n-tiles, 25 m-tiles, 43 joints), 512 threads, 1 CTA/SM (128 regs)
// ============================================================================
__global__ __launch_bounds__(NTHR, 1) void motion_main(
    const float* __restrict__ b1,
    const float* __restrict__ W2a, const float* __restrict__ W2b) {
    extern __shared__ char smem[];
    const uint32_t sb = smem_u32(smem);
    const int tid = threadIdx.x, lane = tid & 31, wid = tid >> 5;
    const int ntile = blockIdx.x, mtile = blockIdx.y, j = blockIdx.z;
    const int m0 = mtile * MT;
    const int warp_m = wid >> 3, warp_n = wid & 7;   // 2 x 8 warp grid

    float* b1s = reinterpret_cast<float*>(smem + OFF_B1);
    float* w2s = reinterpret_cast<float*>(smem + OFF_W2);
    float* red = reinterpret_cast<float*>(smem + OFF_A);   // overlaps A ring

    const int six = (j < J6N);
    const int odim = six ? 6 : 3;
    const int colbase = six ? j * 6 : 78 + (j - J6N) * 3;
    const float* w2p = six ? (W2a + (size_t)j * D_DIM * 6)
                           : (W2b + (size_t)(j - J6N) * D_DIM * 3);

    // ---- stage b1 / W2 n-slices (256 wide) ----
    if (tid < NT) b1s[tid] = b1[(size_t)j * D_DIM + ntile * NT + tid];
#pragma unroll
    for (int it = 0; it < 4; it++) {
        int i = tid + it * NTHR;         // 0..2047
        int n = i >> 3, o = i & 7;
        w2s[n * 8 + o] = (o < odim) ? w2p[(size_t)(ntile * NT + n) * odim + o] : 0.0f;
    }

    // ---- per-thread load constants ----
    const int arow0 = tid >> 3;          // 0..63
    const int akg = tid & 7;             // 16B group within 128B row
    const size_t xoff = (size_t)j * D_DIM + akg * 8;
    const __half* wsrc = g_W1T + ((size_t)j * D_DIM + ntile * NT) * D_DIM;

    // ---- per-lane ldmatrix address constants ----
    const int matA = lane >> 3, rA = lane & 7;
    uint32_t a_row_b[4];
#pragma unroll
    for (int mf = 0; mf < 4; mf++)
        a_row_b[mf] = (uint32_t)((warp_m * 64 + mf * 16 + rA + (matA & 1) * 8) * 128);
    const uint32_t a_kh = (uint32_t)((matA >> 1) * 16);
    // B paired ldsm4: lanes 0-15 -> n-rows block p*16 + rB (k halves 0/16),
    //                 lanes 16-31 -> n-rows block p*16 + 8 + rB
    const int rB = lane & 7;
    uint32_t b_row_b2[2];
#pragma unroll
    for (int p = 0; p < 2; p++)
        b_row_b2[p] = (uint32_t)((warp_n * 32 + p * 16 + ((lane >> 4) & 1) * 8 + rB) * 128);
    const uint32_t b_kh = (uint32_t)(((lane >> 3) & 1) * 16);

    // ---- issue one chunk of cp.async (A 128 rows + B 256 rows) into stage st ----
    auto issue_chunk = [&](int kc, int st) {
#pragma unroll
        for (int it = 0; it < 2; it++) {         // A: 128 rows
            int row = arow0 + 64 * it;
            int gm = m0 + row; if (gm >= BT_TOT) gm = BT_TOT - 1;
            uint32_t off = SWZ((uint32_t)(row * 128 + akg * 16));
            cp_async16(sb + OFF_A + st * 16384 + off,
                       g_xh + (size_t)gm * (J_TOT * D_DIM) + xoff + (size_t)kc * KCH);
        }
#pragma unroll
        for (int it = 0; it < 4; it++) {         // B: 256 rows
            int row = arow0 + 64 * it;
            uint32_t off = SWZ((uint32_t)(row * 128 + akg * 16));
            cp_async16(sb + OFF_B + st * 32768 + off,
                       wsrc + (size_t)row * D_DIM + (size_t)kc * KCH + akg * 8);
        }
    };

    // ---- prologue: prefetch chunks 0 and 1 ----
    issue_chunk(0, 0);
    CP_COMMIT();
    issue_chunk(1, 1);
    CP_COMMIT();
    CP_WAIT1();                 // chunk 0 resident
    __syncthreads();

    float c_[4][4][4];
#pragma unroll
    for (int mf = 0; mf < 4; mf++)
#pragma unroll
        for (int nf = 0; nf < 4; nf++)
#pragma unroll
            for (int e = 0; e < 4; e++) c_[mf][nf][e] = 0.0f;

    // ---- main K loop: 8 chunks of 64, 3-stage ring, prefetch distance 2 ----
    int buf = 0;                       // kc % 3
#pragma unroll 1
    for (int kc = 0; kc < NCHUNK; kc++) {
        const uint32_t sa = sb + OFF_A + buf * 16384;
        const uint32_t sbb = sb + OFF_B + buf * 32768;

        if (kc + 2 < NCHUNK) {
            int st2 = buf + 2; if (st2 >= 3) st2 -= 3;   // (kc+2) % 3
            issue_chunk(kc + 2, st2);
            CP_COMMIT();
        }

#pragma unroll
        for (int s = 0; s < 4; s++) {
            uint32_t ahf[4][4], bf[8];
#pragma unroll
            for (int mf = 0; mf < 4; mf++) {
                uint32_t o = SWZ(a_row_b[mf] + (uint32_t)(s * 32) + a_kh);
                ldsm4(ahf[mf], sa + o);
            }
#pragma unroll
            for (int p = 0; p < 2; p++) {
                uint32_t o = SWZ(b_row_b2[p] + (uint32_t)(s * 32) + b_kh);
                ldsm4(bf + 4 * p, sbb + o);
            }
#pragma unroll
            for (int mf = 0; mf < 4; mf++)
#pragma unroll
                for (int nf = 0; nf < 4; nf++)
                    mma16816(c_[mf][nf], ahf[mf], bf + 2 * nf);
        }

        if (kc < NCHUNK - 1) {
            if (kc + 2 < NCHUNK) { CP_WAIT1(); }   // chunk kc+1 resident
            else                 { CP_WAIT0(); }
            __syncthreads();
        }
        if (++buf == 3) buf = 0;
    }
    __syncthreads();   // ring reads done before red overlay writes

    // ---- epilogue: +b1, GELU(erf), second-layer partial dot, reduce ----
    const int grp = lane >> 2, qid = lane & 3;
#pragma unroll
    for (int mf = 0; mf < 4; mf++) {
        float po[2][6];
#pragma unroll
        for (int hh = 0; hh < 2; hh++)
#pragma unroll
            for (int o = 0; o < 6; o++) po[hh][o] = 0.0f;
#pragma unroll
        for (int nf = 0; nf < 4; nf++) {
            int nl = warp_n * 32 + nf * 8 + qid * 2;
#pragma unroll
            for (int e = 0; e < 4; e++) {
                int nn = nl + (e & 1);
                int hh = e >> 1;
                float hv = c_[mf][nf][e] + b1s[nn];
                float g = 0.5f * hv * (1.0f + erff(hv * 0.70710678118654752f));
#pragma unroll
                for (int o = 0; o < 6; o++)
                    po[hh][o] = fmaf(g, w2s[nn * 8 + o], po[hh][o]);
            }
        }
#pragma unroll
        for (int hh = 0; hh < 2; hh++)
#pragma unroll
            for (int o = 0; o < 6; o++) {
                float v = po[hh][o];
                v += __shfl_xor_sync(0xffffffffu, v, 1);
                v += __shfl_xor_sync(0xffffffffu, v, 2);
                po[hh][o] = v;
            }
        if (qid == 0) {
#pragma unroll
            for (int hh = 0; hh < 2; hh++) {
                int ml = warp_m * 64 + mf * 16 + grp + hh * 8;
#pragma unroll
                for (int o = 0; o < 6; o++)
                    red[warp_n * 768 + ml * 6 + o] = po[hh][o];
            }
        }
    }
    __syncthreads();

    // ---- sum the 8 warp_n partials, write per-n-tile partial to gmem ----
    if (tid < 768) {
        int ml = tid / 6, o = tid % 6;
        float v = 0.0f;
#pragma unroll
        for (int wn = 0; wn < 8; wn++) v += red[wn * 768 + ml * 6 + o];
        int gm = m0 + ml;
        if (gm < BT_TOT && o < odim)
            g_part[ntile][gm][colbase + o] = v;
    }
    if (tid >= 768 - NTHR) {   // second slab (tid+512 in 0..767)
        int i = tid + NTHR - NTHR;   // no-op guard keeps compiler quiet
        (void)i;
    }
    {
        int i = tid + NTHR;          // 512..1023 -> need 512..767
        if (i < 768) {
            int ml = i / 6, o = i % 6;
            float v = 0.0f;
#pragma unroll
            for (int wn = 0; wn < 8; wn++) v += red[wn * 768 + ml * 6 + o];
            int gm = m0 + ml;
            if (gm < BT_TOT && o < odim)
                g_part[ntile][gm][colbase + o] = v;
        }
    }
}

// ============================================================================
// final reduce: out = b2 + sum of 2 n-tile partials (deterministic, no atomics)
// ============================================================================
__global__ __launch_bounds__(256) void reduce_out(const float* __restrict__ b2a,
                                                  const float* __restrict__ b2b,
                                                  float* __restrict__ out) {
    int idx = blockIdx.x * 256 + threadIdx.x;
    if (idx >= BT_TOT * OUT_W) return;
    int m = idx / OUT_W, c = idx % OUT_W;
    float bias = (c < J6N * 6) ? b2a[c] : b2b[c - J6N * 6];
    out[idx] = bias + g_part[0][m][c] + g_part[1][m][c];
}

// ============================================================================
// kernel_launch
// ============================================================================
extern "C" void kernel_launch(void* const* d_in, const int* in_sizes, int n_in,
                              void* d_out, int out_size) {
    (void)in_sizes; (void)n_in; (void)out_size;
    const float* x   = (const float*)d_in[0];
    const float* W1  = (const float*)d_in[1];
    const float* b1  = (const float*)d_in[2];
    const float* W2a = (const float*)d_in[3];
    const float* b2a = (const float*)d_in[4];
    const float* W2b = (const float*)d_in[5];
    const float* b2b = (const float*)d_in[6];
    float* out = (float*)d_out;

    cudaFuncSetAttribute(motion_main,
                         cudaFuncAttributeMaxDynamicSharedMemorySize, SMEM_SZ);

    dim3 pg(16, 16, J_TOT);
    prep_w1<<<pg, dim3(32, 8)>>>(W1);

    size_t nthreads = TOTX / 8;
    prep_x<<<(unsigned)((nthreads + 255) / 256), 256>>>(x);

    dim3 g(2, 25, J_TOT);
    motion_main<<<g, NTHR, SMEM_SZ>>>(b1, W2a, W2b);

    int tot = BT_TOT * OUT_W;
    reduce_out<<<(tot + 255) / 256, 256>>>(b2a, b2b, out);
}

// round 12
// speedup vs baseline: 2.8297x; 1.1505x over previous
#include <cuda_runtime.h>
#include <cuda_fp16.h>
#include <cstdint>
#include <math.h>

// ============================================================================
// MotionDecoder on sm_103 (plain target -> mma.sync HMMA + ldmatrix + cp.async)
//
//   x[16,196,43,512] @ W1[43,512,512] + b1 -> GELU(erf)
//     -> @ W2 (6 or 3 wide) + b2 -> concat [B,T,168]
//
// R12 = R9 base (128x128 tile, 256 thr, 2 CTA/SM, 3-stage ring, single-term
//      fp16; measured 330.3us / rel_err 2.96e-4) + paired-ldsm4 B fragments
//      (validated in R11) + merged prep kernel (w1 transpose hides in x
//      conversion's HBM stream).
// ============================================================================

#define J_TOT  43
#define J6N    13
#define D_DIM  512
#define BT_TOT 3136
#define OUT_W  168

#define MT     128
#define KCH    64
#define NCHUNK 8

#define TOTX  ((size_t)BT_TOT * J_TOT * D_DIM)   // 69,074,944 elems
#define XBLKS 33728                               // ceil(TOTX/8/256)
#define WBLKS (16 * 16 * J_TOT)                   // 11008
#define PREP_BLKS (XBLKS + WBLKS)

// ---- smem byte offsets (dynamic). 3-stage ring ----
#define OFF_AH  0         // [3][128 rows][128B] = 3 x 16 KB   (RED overlaps)
#define OFF_BB  49152     // [3][128 rows][128B] = 3 x 16 KB
#define OFF_B1  98304     // 128 f32
#define OFF_W2  98816     // 128 x 8 f32
#define SMEM_SZ 102912

// ---- persistent scratch (static device arrays; no allocation) ----
__device__ __half g_W1T[(size_t)J_TOT * D_DIM * D_DIM];   // [j][n][d] fp16
__device__ __half g_xh[TOTX];                             // x fp16
__device__ float  g_part[4][BT_TOT][OUT_W];               // per-n-tile partials

#define SWZ(o) ((o) ^ (((o) >> 3) & 0x70))

static __device__ __forceinline__ uint32_t smem_u32(const void* p) {
    uint32_t a;
    asm("{ .reg .u64 t; cvta.to.shared.u64 t, %1; cvt.u32.u64 %0, t; }"
        : "=r"(a) : "l"(p));
    return a;
}

static __device__ __forceinline__ void ldsm4(uint32_t* r, uint32_t addr) {
    asm volatile("ldmatrix.sync.aligned.m8n8.x4.shared.b16 {%0,%1,%2,%3}, [%4];"
                 : "=r"(r[0]), "=r"(r[1]), "=r"(r[2]), "=r"(r[3]) : "r"(addr));
}
static __device__ __forceinline__ void mma16816(float* d, const uint32_t* a,
                                                const uint32_t* b) {
    asm volatile(
        "mma.sync.aligned.m16n8k16.row.col.f32.f16.f16.f32 "
        "{%0,%1,%2,%3}, {%4,%5,%6,%7}, {%8,%9}, {%0,%1,%2,%3};"
        : "+f"(d[0]), "+f"(d[1]), "+f"(d[2]), "+f"(d[3])
        : "r"(a[0]), "r"(a[1]), "r"(a[2]), "r"(a[3]), "r"(b[0]), "r"(b[1]));
}
static __device__ __forceinline__ void cp_async16(uint32_t dst, const void* src) {
    asm volatile("cp.async.cg.shared.global [%0], [%1], 16;"
                 :: "r"(dst), "l"(__cvta_generic_to_global(src)) : "memory");
}
#define CP_COMMIT() asm volatile("cp.async.commit_group;" ::: "memory")
#define CP_WAIT0()  asm volatile("cp.async.wait_group 0;" ::: "memory")
#define CP_WAIT1()  asm volatile("cp.async.wait_group 1;" ::: "memory")

// ============================================================================
// prep_all: blocks [0, XBLKS) convert x fp32->fp16; blocks [XBLKS, ..) do the
// W1 transpose+convert. One launch so both memory streams overlap.
// ============================================================================
__global__ __launch_bounds__(256) void prep_all(const float* __restrict__ x,
                                                const float* __restrict__ W1) {
    if (blockIdx.x < XBLKS) {
        size_t base = ((size_t)blockIdx.x * 256 + threadIdx.x) * 8;
        if (base >= TOTX) return;
        float4 p0 = reinterpret_cast<const float4*>(x + base)[0];
        float4 p1 = reinterpret_cast<const float4*>(x + base)[1];
        __half2 h0 = __floats2half2_rn(p0.x, p0.y);
        __half2 h1 = __floats2half2_rn(p0.z, p0.w);
        __half2 h2 = __floats2half2_rn(p1.x, p1.y);
        __half2 h3 = __floats2half2_rn(p1.z, p1.w);
        uint4 uh;
        uh.x = *reinterpret_cast<uint32_t*>(&h0);
        uh.y = *reinterpret_cast<uint32_t*>(&h1);
        uh.z = *reinterpret_cast<uint32_t*>(&h2);
        uh.w = *reinterpret_cast<uint32_t*>(&h3);
        *reinterpret_cast<uint4*>(g_xh + base) = uh;
    } else {
        __shared__ float tile[32][33];
        int bid = blockIdx.x - XBLKS;          // 0..11007
        int j = bid >> 8;                       // /256
        int rem = bid & 255;
        int n0 = (rem >> 4) * 32, d0 = (rem & 15) * 32;
        int tx = threadIdx.x & 31, ty = threadIdx.x >> 5;   // 32 x 8
        const float* src = W1 + (size_t)j * D_DIM * D_DIM;
#pragma unroll
        for (int i = 0; i < 4; i++)
            tile[ty + 8 * i][tx] = src[(size_t)(d0 + ty + 8 * i) * D_DIM + n0 + tx];
        __syncthreads();
        __half* dst = g_W1T + (size_t)j * D_DIM * D_DIM;
#pragma unroll
        for (int i = 0; i < 4; i++) {
            int n = n0 + ty + 8 * i, d = d0 + tx;
            dst[(size_t)n * D_DIM + d] = __float2half(tile[tx][ty + 8 * i]);
        }
    }
}

// ============================================================================
// main GEMM + fused GELU + second-layer partials
// grid: (4 n-tiles, 25 m-tiles, 43 joints), 256 threads, 2 CTAs/SM
// ============================================================================
__global__ __launch_bounds__(256, 2) void motion_main(
    const float* __restrict__ b1,
    const float* __restrict__ W2a, const float* __restrict__ W2b) {
    extern __shared__ char smem[];
    const uint32_t sb = smem_u32(smem);
    const int tid = threadIdx.x, lane = tid & 31, wid = tid >> 5;
    const int ntile = blockIdx.x, mtile = blockIdx.y, j = blockIdx.z;
    const int m0 = mtile * MT;
    const int warp_m = wid >> 2, warp_n = wid & 3;   // 2 x 4 warp grid

    float* b1s = reinterpret_cast<float*>(smem + OFF_B1);
    float* w2s = reinterpret_cast<float*>(smem + OFF_W2);
    float* red = reinterpret_cast<float*>(smem + OFF_AH);   // overlaps A ring

    const int six = (j < J6N);
    const int odim = six ? 6 : 3;
    const int colbase = six ? j * 6 : 78 + (j - J6N) * 3;
    const float* w2p = six ? (W2a + (size_t)j * D_DIM * 6)
                           : (W2b + (size_t)(j - J6N) * D_DIM * 3);

    // ---- stage b1 / W2 n-slices ----
    if (tid < 128) b1s[tid] = b1[(size_t)j * D_DIM + ntile * 128 + tid];
#pragma unroll
    for (int it = 0; it < 4; it++) {
        int i = tid + it * 256;          // 0..1023
        int n = i >> 3, o = i & 7;
        w2s[n * 8 + o] = (o < odim) ? w2p[(size_t)(ntile * 128 + n) * odim + o] : 0.0f;
    }

    // ---- per-thread load constants ----
    const int arow0 = tid >> 3;          // row base; rows arow0 + 32*it
    const int akg = tid & 7;             // 16B group within 128B row
    const size_t xoff = (size_t)j * D_DIM + akg * 8;
    const __half* wsrc = g_W1T + ((size_t)j * D_DIM + ntile * 128) * D_DIM;

    // ---- per-lane ldmatrix address constants ----
    const int matA = lane >> 3, rA = lane & 7;
    uint32_t a_row_b[4];
#pragma unroll
    for (int mf = 0; mf < 4; mf++)
        a_row_b[mf] = (uint32_t)((warp_m * 64 + mf * 16 + rA + (matA & 1) * 8) * 128);
    const uint32_t a_kh = (uint32_t)((matA >> 1) * 16);
    // B paired ldsm4 (validated R11): two x4 loads cover the 4 n-frags
    const int rB = lane & 7;
    uint32_t b_row_b2[2];
#pragma unroll
    for (int p = 0; p < 2; p++)
        b_row_b2[p] = (uint32_t)((warp_n * 32 + p * 16 + ((lane >> 4) & 1) * 8 + rB) * 128);
    const uint32_t b_kh = (uint32_t)(((lane >> 3) & 1) * 16);

    // ---- issue one chunk of cp.async (AH + BB) into ring stage `st` ----
    auto issue_chunk = [&](int kc, int st) {
#pragma unroll
        for (int it = 0; it < 4; it++) {
            int row = arow0 + 32 * it;
            int gm = m0 + row; if (gm >= BT_TOT) gm = BT_TOT - 1;
            uint32_t off = SWZ((uint32_t)(row * 128 + akg * 16));
            size_t gsrc = (size_t)gm * (J_TOT * D_DIM) + xoff + (size_t)kc * KCH;
            cp_async16(sb + OFF_AH + st * 16384 + off, g_xh + gsrc);
            cp_async16(sb + OFF_BB + st * 16384 + off,
                       wsrc + (size_t)row * D_DIM + (size_t)kc * KCH + akg * 8);
        }
    };

    // ---- prologue: prefetch chunks 0 and 1 ----
    issue_chunk(0, 0);
    CP_COMMIT();
    issue_chunk(1, 1);
    CP_COMMIT();
    CP_WAIT1();                 // chunk 0 resident
    __syncthreads();

    float c_[4][4][4];
#pragma unroll
    for (int mf = 0; mf < 4; mf++)
#pragma unroll
        for (int nf = 0; nf < 4; nf++)
#pragma unroll
            for (int e = 0; e < 4; e++) c_[mf][nf][e] = 0.0f;

    // ---- main K loop: 8 chunks of 64, 3-stage ring, prefetch distance 2 ----
    int buf = 0;                       // kc % 3
#pragma unroll 1
    for (int kc = 0; kc < NCHUNK; kc++) {
        const uint32_t ah = sb + OFF_AH + buf * 16384;
        const uint32_t bb = sb + OFF_BB + buf * 16384;

        if (kc + 2 < NCHUNK) {
            int st2 = buf + 2; if (st2 >= 3) st2 -= 3;   // (kc+2) % 3
            issue_chunk(kc + 2, st2);
            CP_COMMIT();
        }

#pragma unroll
        for (int s = 0; s < 4; s++) {
            uint32_t ahf[4][4], bf[8];
#pragma unroll
            for (int mf = 0; mf < 4; mf++) {
                uint32_t o = SWZ(a_row_b[mf] + (uint32_t)(s * 32) + a_kh);
                ldsm4(ahf[mf], ah + o);
            }
#pragma unroll
            for (int p = 0; p < 2; p++) {
                uint32_t o = SWZ(b_row_b2[p] + (uint32_t)(s * 32) + b_kh);
                ldsm4(bf + 4 * p, bb + o);
            }
#pragma unroll
            for (int mf = 0; mf < 4; mf++)
#pragma unroll
                for (int nf = 0; nf < 4; nf++)
                    mma16816(c_[mf][nf], ahf[mf], bf + 2 * nf);
        }

        if (kc < NCHUNK - 1) {
            if (kc + 2 < NCHUNK) { CP_WAIT1(); }   // chunk kc+1 resident
            else                 { CP_WAIT0(); }
            __syncthreads();
        }
        if (++buf == 3) buf = 0;
    }
    __syncthreads();   // all ring reads done before red overlay writes

    // ---- epilogue: +b1, GELU(erf), second-layer partial dot, reduce ----
    const int grp = lane >> 2, qid = lane & 3;
#pragma unroll
    for (int mf = 0; mf < 4; mf++) {
        float po[2][6];
#pragma unroll
        for (int hh = 0; hh < 2; hh++)
#pragma unroll
            for (int o = 0; o < 6; o++) po[hh][o] = 0.0f;
#pragma unroll
        for (int nf = 0; nf < 4; nf++) {
            int nl = warp_n * 32 + nf * 8 + qid * 2;
#pragma unroll
            for (int e = 0; e < 4; e++) {
                int nn = nl + (e & 1);
                int hh = e >> 1;
                float hv = c_[mf][nf][e] + b1s[nn];
                float g = 0.5f * hv * (1.0f + erff(hv * 0.70710678118654752f));
#pragma unroll
                for (int o = 0; o < 6; o++)
                    po[hh][o] = fmaf(g, w2s[nn * 8 + o], po[hh][o]);
            }
        }
#pragma unroll
        for (int hh = 0; hh < 2; hh++)
#pragma unroll
            for (int o = 0; o < 6; o++) {
                float v = po[hh][o];
                v += __shfl_xor_sync(0xffffffffu, v, 1);
                v += __shfl_xor_sync(0xffffffffu, v, 2);
                po[hh][o] = v;
            }
        if (qid == 0) {
#pragma unroll
            for (int hh = 0; hh < 2; hh++) {
                int ml = warp_m * 64 + mf * 16 + grp + hh * 8;
#pragma unroll
                for (int o = 0; o < 6; o++)
                    red[warp_n * 768 + ml * 6 + o] = po[hh][o];
            }
        }
    }
    __syncthreads();

#pragma unroll
    for (int it = 0; it < 3; it++) {
        int i = tid + it * 256;                 // 0..767
        int ml = i / 6, o = i % 6;
        float v = red[ml * 6 + o] + red[768 + ml * 6 + o] +
                  red[1536 + ml * 6 + o] + red[2304 + ml * 6 + o];
        int gm = m0 + ml;
        if (gm < BT_TOT && o < odim)
            g_part[ntile][gm][colbase + o] = v;
    }
}

// ============================================================================
// final reduce: out = b2 + sum of 4 n-tile partials (deterministic, no atomics)
// ============================================================================
__global__ __launch_bounds__(256) void reduce_out(const float* __restrict__ b2a,
                                                  const float* __restrict__ b2b,
                                                  float* __restrict__ out) {
    int idx = blockIdx.x * 256 + threadIdx.x;
    if (idx >= BT_TOT * OUT_W) return;
    int m = idx / OUT_W, c = idx % OUT_W;
    float bias = (c < J6N * 6) ? b2a[c] : b2b[c - J6N * 6];
    out[idx] = bias + g_part[0][m][c] + g_part[1][m][c] +
               g_part[2][m][c] + g_part[3][m][c];
}

// ============================================================================
// kernel_launch
// ============================================================================
extern "C" void kernel_launch(void* const* d_in, const int* in_sizes, int n_in,
                              void* d_out, int out_size) {
    (void)in_sizes; (void)n_in; (void)out_size;
    const float* x   = (const float*)d_in[0];
    const float* W1  = (const float*)d_in[1];
    const float* b1  = (const float*)d_in[2];
    const float* W2a = (const float*)d_in[3];
    const float* b2a = (const float*)d_in[4];
    const float* W2b = (const float*)d_in[5];
    const float* b2b = (const float*)d_in[6];
    float* out = (float*)d_out;

    cudaFuncSetAttribute(motion_main,
                         cudaFuncAttributeMaxDynamicSharedMemorySize, SMEM_SZ);

    prep_all<<<PREP_BLKS, 256>>>(x, W1);

    dim3 g(4, 25, J_TOT);
    motion_main<<<g, 256, SMEM_SZ>>>(b1, W2a, W2b);

    int tot = BT_TOT * OUT_W;
    reduce_out<<<(tot + 255) / 256, 256>>>(b2a, b2b, out);
}